// round 2
// baseline (speedup 1.0000x reference)
#include <cuda_runtime.h>
#include <math.h>

#define BN 64
#define CN 512
#define HW 784
#define HW4 196
#define NSEG 8
#define CSEG 64
#define FEPS 1e-12f

// ---------------- scratch (static __device__, no allocation) ----------------
__device__ float g_y[NSEG * BN * HW];     // partial y: [seg][b][784]
__device__ float g_vec[5][BN * CN];       // 0,1: ping-pong; 2: u4; 3: v; 4: x2
__device__ float g_nrm2[8][BN];           // 0: ||x0||^2, 1..4: ||u_k||^2, 5: const 1.0
__device__ float g_sc[5][BN];             // 0:num5 1:den5 2:numA 3:den6 4:largest

// ---------------- init: zero accumulators, set unit-norm slot ----------------
__global__ void k_init() {
    int t = threadIdx.x;                       // 512 threads
    if (t < 8 * BN) ((float*)g_nrm2)[t] = (t / BN == 5) ? 1.0f : 0.0f;
    if (t < 4 * BN) ((float*)g_sc)[t] = 0.0f;
}

// ---------------- ||x0||^2 per batch ----------------
__global__ void k_n0(const float* __restrict__ x0) {
    __shared__ float red[16];
    int b = blockIdx.x, t = threadIdx.x;       // 512 threads = C
    float v = x0[b * CN + t];
    float s = v * v;
    #pragma unroll
    for (int o = 16; o; o >>= 1) s += __shfl_xor_sync(0xffffffffu, s, o);
    if ((t & 31) == 0) red[t >> 5] = s;
    __syncthreads();
    if (t < 16) {
        s = red[t];
        #pragma unroll
        for (int o = 8; o; o >>= 1) s += __shfl_xor_sync(0xffffu, s, o);
        if (t == 0) g_nrm2[0][b] = s;
    }
}

// ---------------- S1: y[seg][b][d] = sum_{c in seg} A[b][c][d] * xhat[b][c] --
__global__ void k_s1(const float4* __restrict__ A4, const float* __restrict__ x0in,
                     int xsel, int nslot) {
    int b = blockIdx.x >> 3, seg = blockIdx.x & 7;
    int t = threadIdx.x;                       // 224 threads, 196 active
    if (t >= HW4) return;
    const float* xp = ((xsel < 0) ? (x0in + b * CN) : (&g_vec[xsel][b * CN])) + seg * CSEG;
    float scale = 1.0f / fmaxf(sqrtf(g_nrm2[nslot][b]), FEPS);
    const float4* Ab = A4 + (size_t)(b * CN + seg * CSEG) * HW4 + t;
    float ax = 0.f, ay = 0.f, az = 0.f, aw = 0.f;
    #pragma unroll 8
    for (int c = 0; c < CSEG; c++) {
        float xv = xp[c] * scale;
        float4 a = Ab[(size_t)c * HW4];
        ax += a.x * xv; ay += a.y * xv; az += a.z * xv; aw += a.w * xv;
    }
    float4 r; r.x = ax; r.y = ay; r.z = az; r.w = aw;
    ((float4*)g_y)[(seg * BN + b) * HW4 + t] = r;
}

// ---------------- S2: z[b][c] = A[b][c][:] . y[b][:]  (+ fused reductions) ---
// mode 0: store z to g_vec[zsel], accumulate ||z||^2 into g_nrm2[a1]
// mode 1: store v to g_vec[zsel], accumulate num5 += v*x1, den5 += x1^2
//         (x1 = g_vec[xrefsel] * 1/max(sqrt(g_nrm2[xrefn]),eps))
// mode 2: accumulate numA += t*x2, den6 += x2^2  (x2 = g_vec[xrefsel], unit)
__global__ void k_s2(const float4* __restrict__ A4, int mode, int zsel,
                     int a1, int a2, int xrefsel, int xrefn) {
    __shared__ float ys[HW];
    __shared__ float r1[8], r2[8];
    int b = blockIdx.x >> 2, cq = blockIdx.x & 3;
    int t = threadIdx.x, warp = t >> 5, lane = t & 31;   // 256 threads

    for (int i = t; i < HW; i += 256) {
        float s = 0.f;
        #pragma unroll
        for (int sg = 0; sg < NSEG; sg++) s += g_y[(sg * BN + b) * HW + i];
        ys[i] = s;
    }
    __syncthreads();

    const float4* ys4 = (const float4*)ys;
    float scal = 1.0f;
    if (mode == 1) scal = 1.0f / fmaxf(sqrtf(g_nrm2[xrefn][b]), FEPS);

    float la1 = 0.f, la2 = 0.f;
    for (int r = warp; r < 128; r += 8) {
        int c = cq * 128 + r;
        const float4* Ar = A4 + (size_t)(b * CN + c) * HW4;
        float ax = 0.f, ay = 0.f, az = 0.f, aw = 0.f;
        #pragma unroll
        for (int k = 0; k < 6; k++) {
            int idx = k * 32 + lane;
            float4 a = Ar[idx]; float4 y = ys4[idx];
            ax += a.x * y.x; ay += a.y * y.y; az += a.z * y.z; aw += a.w * y.w;
        }
        if (lane < 4) {
            int idx = 192 + lane;
            float4 a = Ar[idx]; float4 y = ys4[idx];
            ax += a.x * y.x; ay += a.y * y.y; az += a.z * y.z; aw += a.w * y.w;
        }
        float s = (ax + ay) + (az + aw);
        #pragma unroll
        for (int o = 16; o; o >>= 1) s += __shfl_xor_sync(0xffffffffu, s, o);
        if (lane == 0) {
            if (mode == 0) {
                g_vec[zsel][b * CN + c] = s;
                la1 += s * s;
            } else if (mode == 1) {
                g_vec[zsel][b * CN + c] = s;
                float xc = g_vec[xrefsel][b * CN + c] * scal;
                la1 += s * xc; la2 += xc * xc;
            } else {
                float xc = g_vec[xrefsel][b * CN + c];
                la1 += s * xc; la2 += xc * xc;
            }
        }
    }
    if (lane == 0) { r1[warp] = la1; r2[warp] = la2; }
    __syncthreads();
    if (t == 0) {
        float s1 = 0.f, s2 = 0.f;
        #pragma unroll
        for (int w = 0; w < 8; w++) { s1 += r1[w]; s2 += r2[w]; }
        if (mode == 0) {
            atomicAdd(&g_nrm2[a1][b], s1);
        } else {
            atomicAdd(&g_sc[a1][b], s1);
            atomicAdd(&g_sc[a2][b], s2);
        }
    }
}

// ---------------- K5: largest, w = v - largest*x1, x2 = w/||w|| --------------
__global__ void k_k5() {
    __shared__ float red[16];
    __shared__ float wtot;
    int b = blockIdx.x, t = threadIdx.x;       // 512 threads
    float inv4 = 1.0f / fmaxf(sqrtf(g_nrm2[4][b]), FEPS);
    float largest = g_sc[0][b] / g_sc[1][b];
    float x1c = g_vec[2][b * CN + t] * inv4;
    float w = g_vec[3][b * CN + t] - largest * x1c;
    float s = w * w;
    #pragma unroll
    for (int o = 16; o; o >>= 1) s += __shfl_xor_sync(0xffffffffu, s, o);
    if ((t & 31) == 0) red[t >> 5] = s;
    __syncthreads();
    if (t < 16) {
        s = red[t];
        #pragma unroll
        for (int o = 8; o; o >>= 1) s += __shfl_xor_sync(0xffffu, s, o);
        if (t == 0) wtot = s;
    }
    __syncthreads();
    float wn = fmaxf(sqrtf(wtot), FEPS);
    g_vec[4][b * CN + t] = w / wn;
    if (t == 0) g_sc[4][b] = largest;
}

// ---------------- final: penalty = sum_b (largest/smallest - 1)^2 / B --------
__global__ void k_fin(float* __restrict__ out) {
    __shared__ float red[2];
    int t = threadIdx.x;                        // 64 threads
    float largest = g_sc[4][t];
    float tmp = g_sc[2][t] / g_sc[3][t] - largest;
    float smallest = tmp + largest;
    float r = largest / smallest - 1.0f;
    float p = r * r;
    #pragma unroll
    for (int o = 16; o; o >>= 1) p += __shfl_xor_sync(0xffffffffu, p, o);
    if ((t & 31) == 0) red[t >> 5] = p;
    __syncthreads();
    if (t == 0) out[0] = (red[0] + red[1]) / (float)BN;
}

// ---------------- launch ----------------
extern "C" void kernel_launch(void* const* d_in, const int* in_sizes, int n_in,
                              void* d_out, int out_size) {
    const float* A  = (const float*)d_in[0];
    const float* x0 = (const float*)d_in[1];
    if (n_in >= 2 && in_sizes[0] < in_sizes[1]) {   // safety: A is the big one
        const float* t = A; A = x0; x0 = t;
    }
    const float4* A4 = (const float4*)A;
    float* out = (float*)d_out;
    (void)out_size;

    k_init<<<1, 512>>>();
    k_n0<<<BN, CN>>>(x0);

    // P1..P4: power iterations (xi = normalize(AAT xi)), last yields u4
    k_s1<<<BN * NSEG, 224>>>(A4, x0, -1, 0);
    k_s2<<<BN * 4, 256>>>(A4, 0, 0, 1, 0, 0, 0);
    k_s1<<<BN * NSEG, 224>>>(A4, x0, 0, 1);
    k_s2<<<BN * 4, 256>>>(A4, 0, 1, 2, 0, 0, 0);
    k_s1<<<BN * NSEG, 224>>>(A4, x0, 1, 2);
    k_s2<<<BN * 4, 256>>>(A4, 0, 0, 3, 0, 0, 0);
    k_s1<<<BN * NSEG, 224>>>(A4, x0, 0, 3);
    k_s2<<<BN * 4, 256>>>(A4, 0, 2, 4, 0, 0, 0);   // -> u4 in g_vec[2]

    // P5: v = AAT x1 ; num5 = v.x1, den5 = ||x1||^2
    k_s1<<<BN * NSEG, 224>>>(A4, x0, 2, 4);
    k_s2<<<BN * 4, 256>>>(A4, 1, 3, 0, 1, 2, 4);   // v -> g_vec[3]

    // largest, x2
    k_k5<<<BN, CN>>>();

    // P6: t = AAT x2 ; numA = t.x2, den6 = ||x2||^2
    k_s1<<<BN * NSEG, 224>>>(A4, x0, 4, 5);
    k_s2<<<BN * 4, 256>>>(A4, 2, 0, 2, 3, 4, 0);

    k_fin<<<1, 64>>>(out);
}

// round 3
// speedup vs baseline: 1.8073x; 1.8073x over previous
#include <cuda_runtime.h>
#include <math.h>

#define BN 64
#define CN 512
#define HW 784
#define HW4 196
#define NSEG 8
#define CSEG 64
#define FEPS 1e-12f

// ---------------- scratch (static __device__, no allocation) ----------------
__device__ float g_Ya[NSEG * BN * HW];    // ping: Y0, Y2, Y4 (= Wm^T z, unnormalized)
__device__ float g_Yb[NSEG * BN * HW];    // pong: Y1, Y3, Y5
__device__ float g_vec[3][BN * CN];       // 0: u4 (raw z4), 1: v (raw AAT x1), 2: x2 (unit)
__device__ float g_nrm2[8][BN];           // 0:||x0||^2, 1..4:||z_k||^2, 5: const 1.0
__device__ float g_sc[8][BN];             // 0:num5 1:den5 2:num6 3:den6 4:largest 5:invw

// ---------------- init: zero accumulators, set unit-norm slot ----------------
__global__ void k_init() {
    int t = threadIdx.x;                       // 512 threads
    if (t < 8 * BN) ((float*)g_nrm2)[t] = (t / BN == 5) ? 1.0f : 0.0f;
    if (t < 4 * BN) ((float*)g_sc)[t] = 0.0f;
}

// ---------------- ||x0||^2 per batch ----------------
__global__ void k_n0(const float* __restrict__ x0) {
    __shared__ float red[16];
    int b = blockIdx.x, t = threadIdx.x;       // 512 threads = C
    float v = x0[b * CN + t];
    float s = v * v;
    #pragma unroll
    for (int o = 16; o; o >>= 1) s += __shfl_xor_sync(0xffffffffu, s, o);
    if ((t & 31) == 0) red[t >> 5] = s;
    __syncthreads();
    if (t < 16) {
        s = red[t];
        #pragma unroll
        for (int o = 8; o; o >>= 1) s += __shfl_xor_sync(0xffffu, s, o);
        if (t == 0) g_nrm2[0][b] = s;
    }
}

// ---------------- S1 (only for x0): Y0[seg][b][d] = sum_{c in seg} A[b][c][d]*x0[b][c]
__global__ void k_s1(const float4* __restrict__ A4, const float* __restrict__ x0in) {
    int b = blockIdx.x >> 3, seg = blockIdx.x & 7;
    int t = threadIdx.x;                       // 224 threads, 196 active
    if (t >= HW4) return;
    const float* xp = x0in + b * CN + seg * CSEG;
    const float4* Ab = A4 + (size_t)(b * CN + seg * CSEG) * HW4 + t;
    float ax = 0.f, ay = 0.f, az = 0.f, aw = 0.f;
    #pragma unroll 8
    for (int c = 0; c < CSEG; c++) {
        float xv = xp[c];
        float4 a = Ab[(size_t)c * HW4];
        ax += a.x * xv; ay += a.y * xv; az += a.z * xv; aw += a.w * xv;
    }
    float4 r; r.x = ax; r.y = ay; r.z = az; r.w = aw;
    ((float4*)g_Ya)[(seg * BN + b) * HW4 + t] = r;
}

// ---------------- fused apply: z = Wm * ys ; Ynext = Wm^T z ; reductions -----
// ys built from Yin (summed over segments) with normalization scale.
// mode 0: reduction ||z||^2 -> g_nrm2[a1]; optional z store
// mode 1: store v=z; num5 += z*x1, den5 += x1^2   (x1 = u4 * invu4)
// mode 2: ys = (sumYb - largest*invu4*sumYa)*invw ; num6 += z*x2, den6 += x2^2
__global__ void __launch_bounds__(256) k_ap(
        const float4* __restrict__ A4, int yinSel, int youtSel, int zSel,
        int mode, int nsIn, int a1, int a2)
{
    __shared__ float ys[HW];
    __shared__ float yw[8][HW];
    __shared__ float r1s[8], r2s[8];
    int b = blockIdx.x >> 3, seg = blockIdx.x & 7;
    int t = threadIdx.x, warp = t >> 5, lane = t & 31;   // 256 threads

    // --- build ys in shared ---
    if (mode < 2) {
        const float* Yin = yinSel ? g_Yb : g_Ya;
        float s = 1.0f / fmaxf(sqrtf(g_nrm2[nsIn][b]), FEPS);
        for (int i = t; i < HW; i += 256) {
            float acc = 0.f;
            #pragma unroll
            for (int sg = 0; sg < NSEG; sg++) acc += Yin[(sg * BN + b) * HW + i];
            ys[i] = acc * s;
        }
    } else {
        float invu4 = 1.0f / fmaxf(sqrtf(g_nrm2[4][b]), FEPS);
        float largest = g_sc[4][b];
        float invw = g_sc[5][b];
        float f4 = largest * invu4;
        for (int i = t; i < HW; i += 256) {
            float a5 = 0.f, a4 = 0.f;
            #pragma unroll
            for (int sg = 0; sg < NSEG; sg++) {
                a5 += g_Yb[(sg * BN + b) * HW + i];
                a4 += g_Ya[(sg * BN + b) * HW + i];
            }
            ys[i] = (a5 - f4 * a4) * invw;
        }
    }
    __syncthreads();

    const float4* ys4 = (const float4*)ys;
    bool k6 = (lane < 4);
    float4 acc[7];
    #pragma unroll
    for (int k = 0; k < 7; k++) acc[k] = make_float4(0.f, 0.f, 0.f, 0.f);
    float la1 = 0.f, la2 = 0.f;
    float invu4 = (mode == 1) ? 1.0f / fmaxf(sqrtf(g_nrm2[nsIn][b]), FEPS) : 1.0f;
    float* zout = (zSel >= 0) ? &g_vec[zSel][0] : (float*)0;

    int c0 = seg * CSEG + warp * 8;
    for (int r = 0; r < 8; r++) {
        int c = c0 + r;
        const float4* Ar = A4 + (size_t)(b * CN + c) * HW4;
        float4 a[7];
        float d0 = 0.f, d1 = 0.f, d2 = 0.f, d3 = 0.f;
        #pragma unroll
        for (int k = 0; k < 6; k++) {
            int idx = k * 32 + lane;
            a[k] = Ar[idx];
            float4 y = ys4[idx];
            d0 += a[k].x * y.x; d1 += a[k].y * y.y;
            d2 += a[k].z * y.z; d3 += a[k].w * y.w;
        }
        if (k6) {
            int idx = 192 + lane;
            a[6] = Ar[idx];
            float4 y = ys4[idx];
            d0 += a[6].x * y.x; d1 += a[6].y * y.y;
            d2 += a[6].z * y.z; d3 += a[6].w * y.w;
        } else {
            a[6] = make_float4(0.f, 0.f, 0.f, 0.f);
        }
        float z = (d0 + d1) + (d2 + d3);
        #pragma unroll
        for (int o = 16; o; o >>= 1) z += __shfl_xor_sync(0xffffffffu, z, o);

        // axpy into Ynext accumulators (A row still in registers)
        #pragma unroll
        for (int k = 0; k < 7; k++) {
            acc[k].x += z * a[k].x; acc[k].y += z * a[k].y;
            acc[k].z += z * a[k].z; acc[k].w += z * a[k].w;
        }
        if (lane == 0) {
            if (mode == 0) {
                if (zout) zout[b * CN + c] = z;
                la1 += z * z;
            } else if (mode == 1) {
                zout[b * CN + c] = z;
                float xc = g_vec[0][b * CN + c] * invu4;
                la1 += z * xc; la2 += xc * xc;
            } else {
                float xc = g_vec[2][b * CN + c];
                la1 += z * xc; la2 += xc * xc;
            }
        }
    }

    // --- warp partials -> block sum -> Yout ---
    if (youtSel >= 0) {
        float4* yo = (float4*)yw[warp];
        #pragma unroll
        for (int k = 0; k < 6; k++) yo[k * 32 + lane] = acc[k];
        if (k6) yo[192 + lane] = acc[6];
    }
    if (lane == 0) { r1s[warp] = la1; r2s[warp] = la2; }
    __syncthreads();
    if (youtSel >= 0) {
        float* Yout = youtSel ? g_Yb : g_Ya;
        for (int i = t; i < HW; i += 256) {
            float s = 0.f;
            #pragma unroll
            for (int w = 0; w < 8; w++) s += yw[w][i];
            Yout[(seg * BN + b) * HW + i] = s;
        }
    }
    if (t == 0) {
        float s1 = 0.f, s2 = 0.f;
        #pragma unroll
        for (int w = 0; w < 8; w++) { s1 += r1s[w]; s2 += r2s[w]; }
        if (mode == 0) {
            atomicAdd(&g_nrm2[a1][b], s1);
        } else {
            atomicAdd(&g_sc[a1][b], s1);
            atomicAdd(&g_sc[a2][b], s2);
        }
    }
}

// ---------------- K5: largest, w = v - largest*x1, x2 = w/||w||, invw --------
__global__ void k_k5() {
    __shared__ float red[16];
    __shared__ float wtot;
    int b = blockIdx.x, t = threadIdx.x;       // 512 threads
    float inv4 = 1.0f / fmaxf(sqrtf(g_nrm2[4][b]), FEPS);
    float largest = g_sc[0][b] / g_sc[1][b];
    float x1c = g_vec[0][b * CN + t] * inv4;
    float w = g_vec[1][b * CN + t] - largest * x1c;
    float s = w * w;
    #pragma unroll
    for (int o = 16; o; o >>= 1) s += __shfl_xor_sync(0xffffffffu, s, o);
    if ((t & 31) == 0) red[t >> 5] = s;
    __syncthreads();
    if (t < 16) {
        s = red[t];
        #pragma unroll
        for (int o = 8; o; o >>= 1) s += __shfl_xor_sync(0xffffu, s, o);
        if (t == 0) wtot = s;
    }
    __syncthreads();
    float invw = 1.0f / fmaxf(sqrtf(wtot), FEPS);
    g_vec[2][b * CN + t] = w * invw;
    if (t == 0) { g_sc[4][b] = largest; g_sc[5][b] = invw; }
}

// ---------------- final: penalty = sum_b (largest/smallest - 1)^2 / B --------
__global__ void k_fin(float* __restrict__ out) {
    __shared__ float red[2];
    int t = threadIdx.x;                        // 64 threads
    float largest = g_sc[4][t];
    float tmp = g_sc[2][t] / g_sc[3][t] - largest;
    float smallest = tmp + largest;
    float r = largest / smallest - 1.0f;
    float p = r * r;
    #pragma unroll
    for (int o = 16; o; o >>= 1) p += __shfl_xor_sync(0xffffffffu, p, o);
    if ((t & 31) == 0) red[t >> 5] = p;
    __syncthreads();
    if (t == 0) out[0] = (red[0] + red[1]) / (float)BN;
}

// ---------------- launch ----------------
extern "C" void kernel_launch(void* const* d_in, const int* in_sizes, int n_in,
                              void* d_out, int out_size) {
    const float* A  = (const float*)d_in[0];
    const float* x0 = (const float*)d_in[1];
    if (n_in >= 2 && in_sizes[0] < in_sizes[1]) {   // safety: A is the big one
        const float* t = A; A = x0; x0 = t;
    }
    const float4* A4 = (const float4*)A;
    float* out = (float*)d_out;
    (void)out_size;

    k_init<<<1, 512>>>();
    k_n0<<<BN, CN>>>(x0);

    // Y0 = Wm^T x0 (unnormalized) -> g_Ya          [1 A-sweep]
    k_s1<<<BN * NSEG, 224>>>(A4, x0);

    // applies 1..4: z_k = AAT x_{k-1}hat, fused Ynext   [4 A-sweeps]
    k_ap<<<BN * NSEG, 256>>>(A4, 0, 1, -1, 0, 0, 1, 0);   // z1, Y1->Yb
    k_ap<<<BN * NSEG, 256>>>(A4, 1, 0, -1, 0, 1, 2, 0);   // z2, Y2->Ya
    k_ap<<<BN * NSEG, 256>>>(A4, 0, 1, -1, 0, 2, 3, 0);   // z3, Y3->Yb
    k_ap<<<BN * NSEG, 256>>>(A4, 1, 0,  0, 0, 3, 4, 0);   // z4=u4 store, Y4->Ya

    // apply 5: v = AAT x1; num5=v.x1, den5=||x1||^2; Y5->Yb   [1 A-sweep]
    k_ap<<<BN * NSEG, 256>>>(A4, 0, 1,  1, 1, 4, 0, 1);

    // largest, x2, invw
    k_k5<<<BN, CN>>>();

    // apply 6: t = AAT x2 (ys from Y4,Y5 combo); num6, den6   [1 A-sweep]
    k_ap<<<BN * NSEG, 256>>>(A4, 0, -1, -1, 2, 0, 2, 3);

    k_fin<<<1, 64>>>(out);
}